// round 1
// baseline (speedup 1.0000x reference)
#include <cuda_runtime.h>
#include <cuda_bf16.h>
#include <cstdint>

#define B 512
#define EDIM 200
#define NUM_ENT 100000
#define FDIM 4608          // 32*8*18
#define EPS 1e-5f

// ---------------- device scratch (static allocations only) ----------------
__device__ float d_y[B * FDIM];        // conv output, pre-bn1   (9.4 MB)
__device__ float d_h[B * EDIM];        // fc output, pre-bn2
__device__ float d_zt[EDIM * B];       // bn2+relu output, k-major (transposed)
__device__ float d_chsum[32];
__device__ float d_chsq[32];
__device__ float d_bn0[2];             // {scale, shift}
__device__ float d_bn1a[32];
__device__ float d_bn1c[32];

// ---------------- K0: zero accumulators ----------------
__global__ void k0_zero() {
    int i = blockIdx.x * blockDim.x + threadIdx.x;
    if (i < B * EDIM) d_h[i] = 0.f;
    if (i < 32) { d_chsum[i] = 0.f; d_chsq[i] = 0.f; }
}

// ---------------- K1: bn0 stats over all 512*200 gathered values ----------------
__global__ void k1_bn0(const int* __restrict__ e1, const float* __restrict__ emb,
                       const float* __restrict__ g0, const float* __restrict__ b0) {
    __shared__ float rs[1024], rq[1024];
    int tid = threadIdx.x;
    float s = 0.f, q = 0.f;
    for (int idx = tid; idx < B * EDIM; idx += 1024) {
        int b = idx / EDIM, j = idx - b * EDIM;
        float v = emb[(size_t)e1[b] * EDIM + j];
        s += v; q += v * v;
    }
    rs[tid] = s; rq[tid] = q;
    __syncthreads();
    for (int o = 512; o; o >>= 1) {
        if (tid < o) { rs[tid] += rs[tid + o]; rq[tid] += rq[tid + o]; }
        __syncthreads();
    }
    if (tid == 0) {
        const float inv = 1.f / (float)(B * EDIM);
        float m = rs[0] * inv;
        float var = rq[0] * inv - m * m;
        float sc = rsqrtf(var + EPS) * g0[0];
        d_bn0[0] = sc;
        d_bn0[1] = b0[0] - m * sc;
    }
}

// ---------------- K2: relation-indexed 3x3 conv, per-sample ----------------
// image 10x20 -> out 32ch x 8 x 18. 512 blocks x 256 threads, thread = (o,i) row of 18.
__global__ void k2_conv(const int* __restrict__ e1, const int* __restrict__ rel,
                        const float* __restrict__ emb,
                        const float* __restrict__ conv_w, const float* __restrict__ conv_b) {
    __shared__ float sx[200];
    __shared__ float sw[288];
    __shared__ float scb[32];
    int b = blockIdx.x;
    int tid = threadIdx.x;
    int r = rel[b];
    float bn_s = d_bn0[0], bn_b = d_bn0[1];
    if (tid < 200) sx[tid] = fmaf(emb[(size_t)e1[b] * EDIM + tid], bn_s, bn_b);
    for (int i = tid; i < 288; i += 256) sw[i] = conv_w[(size_t)r * 288 + i];
    if (tid < 32) scb[tid] = conv_b[(size_t)r * 32 + tid];
    __syncthreads();

    int o = tid >> 3;          // channel 0..31
    int i = tid & 7;           // out row 0..7
    const float* w = &sw[o * 9];
    float cb = scb[o];
    float ls = 0.f, lq = 0.f;
    float* yrow = &d_y[(size_t)b * FDIM + o * 144 + i * 18];
    #pragma unroll
    for (int j = 0; j < 18; j++) {
        float acc = cb;
        #pragma unroll
        for (int di = 0; di < 3; di++)
            #pragma unroll
            for (int dj = 0; dj < 3; dj++)
                acc = fmaf(sx[(i + di) * 20 + (j + dj)], w[di * 3 + dj], acc);
        yrow[j] = acc;
        ls += acc; lq += acc * acc;
    }
    // reduce within 8-lane groups (same channel o), then atomic
    #pragma unroll
    for (int off = 4; off; off >>= 1) {
        ls += __shfl_down_sync(0xffffffffu, ls, off, 8);
        lq += __shfl_down_sync(0xffffffffu, lq, off, 8);
    }
    if ((tid & 7) == 0) {
        atomicAdd(&d_chsum[o], ls);
        atomicAdd(&d_chsq[o], lq);
    }
}

// ---------------- K3a: finalize bn1 per-channel affine ----------------
__global__ void k3a_bn1(const float* __restrict__ g1, const float* __restrict__ b1) {
    int c = threadIdx.x;
    if (c < 32) {
        const float inv = 1.f / (float)(B * 144);
        float m = d_chsum[c] * inv;
        float var = d_chsq[c] * inv - m * m;
        float a = rsqrtf(var + EPS) * g1[c];
        d_bn1a[c] = a;
        d_bn1c[c] = b1[c] - m * a;
    }
}

// ---------------- K3: fc GEMM  h[m,n] = sum_k relu(bn1(y[m,k])) * fc_w[n,k] ----------------
// grid (2 ntiles x 8 mtiles x 36 ksplits), Mt=64 Nt=128 Kt=128, atomicAdd into d_h.
#define FC_SY_STRIDE 68
#define FC_SW_STRIDE 132
#define FC_SMEM ((128*FC_SY_STRIDE + 128*FC_SW_STRIDE) * 4)
__global__ void __launch_bounds__(256) k3_fc(const float* __restrict__ fc_w) {
    extern __shared__ float sm[];
    float* s_y = sm;                         // [128k][68]
    float* s_w = sm + 128 * FC_SY_STRIDE;    // [128k][132]
    __shared__ float s_a[32], s_c[32];

    int tid = threadIdx.x;
    int n0 = blockIdx.x * 128, m0 = blockIdx.y * 64, k0 = blockIdx.z * 128;
    if (tid < 32) { s_a[tid] = d_bn1a[tid]; s_c[tid] = d_bn1c[tid]; }
    __syncthreads();

    #pragma unroll
    for (int i = 0; i < 8; i++) {
        int p = tid + i * 256;
        int m = p >> 5, c4 = p & 31;
        float4 v = *(const float4*)&d_y[(size_t)(m0 + m) * FDIM + k0 + c4 * 4];
        int kk = k0 + c4 * 4;
        int ch0 = kk / 144, ch1 = (kk + 1) / 144, ch2 = (kk + 2) / 144, ch3 = (kk + 3) / 144;
        s_y[(c4 * 4 + 0) * FC_SY_STRIDE + m] = fmaxf(fmaf(v.x, s_a[ch0], s_c[ch0]), 0.f);
        s_y[(c4 * 4 + 1) * FC_SY_STRIDE + m] = fmaxf(fmaf(v.y, s_a[ch1], s_c[ch1]), 0.f);
        s_y[(c4 * 4 + 2) * FC_SY_STRIDE + m] = fmaxf(fmaf(v.z, s_a[ch2], s_c[ch2]), 0.f);
        s_y[(c4 * 4 + 3) * FC_SY_STRIDE + m] = fmaxf(fmaf(v.w, s_a[ch3], s_c[ch3]), 0.f);
    }
    #pragma unroll
    for (int i = 0; i < 16; i++) {
        int p = tid + i * 256;
        int n = p >> 5, c4 = p & 31;
        float4 v = make_float4(0.f, 0.f, 0.f, 0.f);
        if (n0 + n < EDIM) v = *(const float4*)&fc_w[(size_t)(n0 + n) * FDIM + k0 + c4 * 4];
        s_w[(c4 * 4 + 0) * FC_SW_STRIDE + n] = v.x;
        s_w[(c4 * 4 + 1) * FC_SW_STRIDE + n] = v.y;
        s_w[(c4 * 4 + 2) * FC_SW_STRIDE + n] = v.z;
        s_w[(c4 * 4 + 3) * FC_SW_STRIDE + n] = v.w;
    }
    __syncthreads();

    int mg = (tid & 15) * 4;
    int ng = (tid >> 4) * 8;
    float acc[32];
    #pragma unroll
    for (int i = 0; i < 32; i++) acc[i] = 0.f;

    #pragma unroll 8
    for (int k = 0; k < 128; k++) {
        float4 z = *(const float4*)(s_y + k * FC_SY_STRIDE + mg);
        float4 ea = *(const float4*)(s_w + k * FC_SW_STRIDE + ng);
        float4 eb = *(const float4*)(s_w + k * FC_SW_STRIDE + ng + 4);
        float zz[4] = {z.x, z.y, z.z, z.w};
        float ee[8] = {ea.x, ea.y, ea.z, ea.w, eb.x, eb.y, eb.z, eb.w};
        #pragma unroll
        for (int mi = 0; mi < 4; mi++)
            #pragma unroll
            for (int nj = 0; nj < 8; nj++)
                acc[mi * 8 + nj] = fmaf(zz[mi], ee[nj], acc[mi * 8 + nj]);
    }

    #pragma unroll
    for (int mi = 0; mi < 4; mi++)
        #pragma unroll
        for (int nj = 0; nj < 8; nj++) {
            int n = n0 + ng + nj;
            if (n < EDIM)
                atomicAdd(&d_h[(size_t)(m0 + mg + mi) * EDIM + n], acc[mi * 8 + nj]);
        }
}

// ---------------- K4: bn2 per-feature + relu, write z transposed (k-major) ----------------
__global__ void k4_bn2(const float* __restrict__ g2, const float* __restrict__ b2) {
    int n = blockIdx.x;
    int t = threadIdx.x;   // 256
    float v0 = d_h[(size_t)t * EDIM + n];
    float v1 = d_h[(size_t)(t + 256) * EDIM + n];
    __shared__ float rs[256], rq[256];
    rs[t] = v0 + v1; rq[t] = v0 * v0 + v1 * v1;
    __syncthreads();
    for (int o = 128; o; o >>= 1) {
        if (t < o) { rs[t] += rs[t + o]; rq[t] += rq[t + o]; }
        __syncthreads();
    }
    __shared__ float sa, sc;
    if (t == 0) {
        float m = rs[0] * (1.f / 512.f);
        float var = rq[0] * (1.f / 512.f) - m * m;
        float a = rsqrtf(var + EPS) * g2[n];
        sa = a; sc = b2[n] - m * a;
    }
    __syncthreads();
    d_zt[n * B + t]       = fmaxf(fmaf(v0, sa, sc), 0.f);
    d_zt[n * B + t + 256] = fmaxf(fmaf(v1, sa, sc), 0.f);
}

// ---------------- K5: logits GEMM + bias + sigmoid ----------------
// out[m,e] = sigmoid( sum_k z[m,k]*emb[e,k] + bias_e[e] ).
// Mt=64, Nt=128, full K=200 (5 chunks of 40). 4m x 8n register tile per thread.
#define SE_STRIDE 132
#define FIN_SMEM ((EDIM*64 + 40*SE_STRIDE) * 4)
__global__ void __launch_bounds__(256) k5_final(const float* __restrict__ emb,
                                                const float* __restrict__ bias_e,
                                                float* __restrict__ out) {
    extern __shared__ float sm[];
    float* s_z = sm;                 // [200][64]
    float* s_e = sm + EDIM * 64;     // [40][132] per chunk
    int tid = threadIdx.x;
    int n0 = blockIdx.x * 128, m0 = blockIdx.y * 64;

    // fill s_z (k-major, contiguous per k)
    #pragma unroll 5
    for (int i = 0; i < 50; i++) {
        int q = tid + i * 256;           // q = k*64 + m
        int k = q >> 6, m = q & 63;
        s_z[q] = d_zt[k * B + m0 + m];
    }

    int mg = (tid & 15) * 4;
    int ng = (tid >> 4) * 8;
    float acc[32];
    #pragma unroll
    for (int i = 0; i < 32; i++) acc[i] = 0.f;

    for (int kc = 0; kc < 5; kc++) {
        int k0 = kc * 40;
        __syncthreads();   // also covers s_z on first iteration
        #pragma unroll
        for (int i = 0; i < 5; i++) {
            int p = tid + i * 256;       // 1280 float4 = 128 rows x 10
            int row = p / 10;
            int c4 = p - row * 10;
            float4 v = make_float4(0.f, 0.f, 0.f, 0.f);
            if (n0 + row < NUM_ENT)
                v = *(const float4*)&emb[(size_t)(n0 + row) * EDIM + k0 + c4 * 4];
            s_e[(c4 * 4 + 0) * SE_STRIDE + row] = v.x;
            s_e[(c4 * 4 + 1) * SE_STRIDE + row] = v.y;
            s_e[(c4 * 4 + 2) * SE_STRIDE + row] = v.z;
            s_e[(c4 * 4 + 3) * SE_STRIDE + row] = v.w;
        }
        __syncthreads();

        #pragma unroll
        for (int k = 0; k < 40; k++) {
            float4 z = *(const float4*)(s_z + (k0 + k) * 64 + mg);
            float4 ea = *(const float4*)(s_e + k * SE_STRIDE + ng);
            float4 eb = *(const float4*)(s_e + k * SE_STRIDE + ng + 4);
            float zz[4] = {z.x, z.y, z.z, z.w};
            float ee[8] = {ea.x, ea.y, ea.z, ea.w, eb.x, eb.y, eb.z, eb.w};
            #pragma unroll
            for (int mi = 0; mi < 4; mi++)
                #pragma unroll
                for (int nj = 0; nj < 8; nj++)
                    acc[mi * 8 + nj] = fmaf(zz[mi], ee[nj], acc[mi * 8 + nj]);
        }
    }

    int nb = n0 + ng;
    if (nb < NUM_ENT) {    // NUM_ENT % 8 == 0 -> group fully valid or fully invalid
        float bs[8];
        #pragma unroll
        for (int j = 0; j < 8; j++) bs[j] = bias_e[nb + j];
        #pragma unroll
        for (int mi = 0; mi < 4; mi++) {
            float o[8];
            #pragma unroll
            for (int j = 0; j < 8; j++) {
                float v = acc[mi * 8 + j] + bs[j];
                o[j] = 1.f / (1.f + __expf(-v));
            }
            size_t off = (size_t)(m0 + mg + mi) * NUM_ENT + nb;
            *(float4*)&out[off]     = make_float4(o[0], o[1], o[2], o[3]);
            *(float4*)&out[off + 4] = make_float4(o[4], o[5], o[6], o[7]);
        }
    }
}

// ---------------- launcher ----------------
extern "C" void kernel_launch(void* const* d_in, const int* in_sizes, int n_in,
                              void* d_out, int out_size) {
    const int*   e1     = (const int*)d_in[0];
    const int*   rel    = (const int*)d_in[1];
    const float* emb    = (const float*)d_in[2];
    const float* conv_w = (const float*)d_in[3];
    const float* conv_b = (const float*)d_in[4];
    const float* g0     = (const float*)d_in[5];
    const float* b0     = (const float*)d_in[6];
    const float* g1     = (const float*)d_in[7];
    const float* b1     = (const float*)d_in[8];
    const float* g2     = (const float*)d_in[9];
    const float* b2     = (const float*)d_in[10];
    const float* fc_w   = (const float*)d_in[11];
    // d_in[12] = fc_b: cancels exactly under training-mode bn2 -> unused
    const float* bias_e = (const float*)d_in[13];
    float* out = (float*)d_out;

    cudaFuncSetAttribute(k3_fc,    cudaFuncAttributeMaxDynamicSharedMemorySize, FC_SMEM);
    cudaFuncSetAttribute(k5_final, cudaFuncAttributeMaxDynamicSharedMemorySize, FIN_SMEM);

    k0_zero<<<400, 256>>>();
    k1_bn0<<<1, 1024>>>(e1, emb, g0, b0);
    k2_conv<<<B, 256>>>(e1, rel, emb, conv_w, conv_b);
    k3a_bn1<<<1, 32>>>(g1, b1);
    k3_fc<<<dim3(2, 8, 36), 256, FC_SMEM>>>(fc_w);
    k4_bn2<<<EDIM, 256>>>(g2, b2);
    k5_final<<<dim3((NUM_ENT + 127) / 128, B / 64), 256, FIN_SMEM>>>(emb, bias_e, out);
}

// round 3
// speedup vs baseline: 1.0431x; 1.0431x over previous
#include <cuda_runtime.h>
#include <cuda_bf16.h>
#include <cstdint>

#define B 512
#define EDIM 200
#define NUM_ENT 100000
#define FDIM 4608          // 32*8*18
#define EPS 1e-5f
#define KCAT 768           // 3 split-terms x 256 (200 padded to 256)
#define ENT_TILE 128
#define N_GRID ((NUM_ENT + ENT_TILE - 1) / ENT_TILE)   // 782
#define ENT_PAD (N_GRID * ENT_TILE)                    // 100096

// ---------------- device scratch (static allocations only) ----------------
__device__ float d_y[B * FDIM];            // conv output, pre-bn1
__device__ float d_h[B * EDIM];            // fc output, pre-bn2
__device__ __nv_bfloat16 d_zcat[B * KCAT];           // [batch][768] = [z_hi|z_lo|z_hi]
__device__ __nv_bfloat16 d_ecat[ENT_PAD * KCAT];     // [ent][768]  = [e_hi|e_hi|e_lo]
__device__ float d_chsum[32];
__device__ float d_chsq[32];
__device__ float d_bn0[2];
__device__ float d_bn1a[32];
__device__ float d_bn1c[32];

// ---------------- PTX helpers (sm_80-compatible subset only) ----------------
__device__ __forceinline__ uint32_t smem_u32(const void* p) {
    uint32_t a;
    asm("{ .reg .u64 t; cvta.to.shared.u64 t, %1; cvt.u32.u64 %0, t; }" : "=r"(a) : "l"(p));
    return a;
}
__device__ __forceinline__ void cp_async16(uint32_t dst, const void* src) {
    asm volatile("cp.async.cg.shared.global [%0], [%1], 16;" :: "r"(dst), "l"(src) : "memory");
}
__device__ __forceinline__ void cp_commit() {
    asm volatile("cp.async.commit_group;" ::: "memory");
}
__device__ __forceinline__ void ldm4(uint32_t* r, uint32_t a) {
    asm volatile("ldmatrix.sync.aligned.m8n8.x4.shared.b16 {%0,%1,%2,%3}, [%4];"
                 : "=r"(r[0]), "=r"(r[1]), "=r"(r[2]), "=r"(r[3]) : "r"(a));
}
__device__ __forceinline__ void mma16816(float* d, const uint32_t* a, const uint32_t* b) {
    asm volatile("mma.sync.aligned.m16n8k16.row.col.f32.bf16.bf16.f32 "
                 "{%0,%1,%2,%3}, {%4,%5,%6,%7}, {%8,%9}, {%0,%1,%2,%3};"
                 : "+f"(d[0]), "+f"(d[1]), "+f"(d[2]), "+f"(d[3])
                 : "r"(a[0]), "r"(a[1]), "r"(a[2]), "r"(a[3]), "r"(b[0]), "r"(b[1]));
}
__device__ __forceinline__ uint32_t swz(uint32_t off) { return off ^ ((off >> 3) & 0x70); }
__device__ __forceinline__ uint32_t pack_bf16(__nv_bfloat16 a, __nv_bfloat16 b) {
    return (uint32_t)__bfloat16_as_ushort(a) | ((uint32_t)__bfloat16_as_ushort(b) << 16);
}

// ---------------- K0: zero accumulators ----------------
__global__ void k0_zero() {
    int i = blockIdx.x * blockDim.x + threadIdx.x;
    if (i < B * EDIM) d_h[i] = 0.f;
    if (i < B * KCAT / 2) ((uint32_t*)d_zcat)[i] = 0u;
    if (i < 32) { d_chsum[i] = 0.f; d_chsq[i] = 0.f; }
}

// ---------------- K1: bn0 stats ----------------
__global__ void k1_bn0(const int* __restrict__ e1, const float* __restrict__ emb,
                       const float* __restrict__ g0, const float* __restrict__ b0) {
    __shared__ float rs[1024], rq[1024];
    int tid = threadIdx.x;
    float s = 0.f, q = 0.f;
    for (int idx = tid; idx < B * EDIM; idx += 1024) {
        int b = idx / EDIM, j = idx - b * EDIM;
        float v = emb[(size_t)e1[b] * EDIM + j];
        s += v; q += v * v;
    }
    rs[tid] = s; rq[tid] = q;
    __syncthreads();
    for (int o = 512; o; o >>= 1) {
        if (tid < o) { rs[tid] += rs[tid + o]; rq[tid] += rq[tid + o]; }
        __syncthreads();
    }
    if (tid == 0) {
        const float inv = 1.f / (float)(B * EDIM);
        float m = rs[0] * inv;
        float var = rq[0] * inv - m * m;
        float sc = rsqrtf(var + EPS) * g0[0];
        d_bn0[0] = sc;
        d_bn0[1] = b0[0] - m * sc;
    }
}

// ---------------- K2: relation-indexed 3x3 conv ----------------
__global__ void k2_conv(const int* __restrict__ e1, const int* __restrict__ rel,
                        const float* __restrict__ emb,
                        const float* __restrict__ conv_w, const float* __restrict__ conv_b) {
    __shared__ float sx[200];
    __shared__ float sw[288];
    __shared__ float scb[32];
    int b = blockIdx.x;
    int tid = threadIdx.x;
    int r = rel[b];
    float bn_s = d_bn0[0], bn_b = d_bn0[1];
    if (tid < 200) sx[tid] = fmaf(emb[(size_t)e1[b] * EDIM + tid], bn_s, bn_b);
    for (int i = tid; i < 288; i += 256) sw[i] = conv_w[(size_t)r * 288 + i];
    if (tid < 32) scb[tid] = conv_b[(size_t)r * 32 + tid];
    __syncthreads();

    int o = tid >> 3;
    int i = tid & 7;
    const float* w = &sw[o * 9];
    float cb = scb[o];
    float ls = 0.f, lq = 0.f;
    float* yrow = &d_y[(size_t)b * FDIM + o * 144 + i * 18];
    #pragma unroll
    for (int j = 0; j < 18; j++) {
        float acc = cb;
        #pragma unroll
        for (int di = 0; di < 3; di++)
            #pragma unroll
            for (int dj = 0; dj < 3; dj++)
                acc = fmaf(sx[(i + di) * 20 + (j + dj)], w[di * 3 + dj], acc);
        yrow[j] = acc;
        ls += acc; lq += acc * acc;
    }
    #pragma unroll
    for (int off = 4; off; off >>= 1) {
        ls += __shfl_down_sync(0xffffffffu, ls, off, 8);
        lq += __shfl_down_sync(0xffffffffu, lq, off, 8);
    }
    if ((tid & 7) == 0) {
        atomicAdd(&d_chsum[o], ls);
        atomicAdd(&d_chsq[o], lq);
    }
}

// ---------------- K3a: bn1 affine ----------------
__global__ void k3a_bn1(const float* __restrict__ g1, const float* __restrict__ b1) {
    int c = threadIdx.x;
    if (c < 32) {
        const float inv = 1.f / (float)(B * 144);
        float m = d_chsum[c] * inv;
        float var = d_chsq[c] * inv - m * m;
        float a = rsqrtf(var + EPS) * g1[c];
        d_bn1a[c] = a;
        d_bn1c[c] = b1[c] - m * a;
    }
}

// ---------------- K3: fc GEMM (fp32 SIMT, k-split atomics) ----------------
#define FC_SY_STRIDE 68
#define FC_SW_STRIDE 132
#define FC_SMEM ((128*FC_SY_STRIDE + 128*FC_SW_STRIDE) * 4)
__global__ void __launch_bounds__(256) k3_fc(const float* __restrict__ fc_w) {
    extern __shared__ float sm[];
    float* s_y = sm;
    float* s_w = sm + 128 * FC_SY_STRIDE;
    __shared__ float s_a[32], s_c[32];

    int tid = threadIdx.x;
    int n0 = blockIdx.x * 128, m0 = blockIdx.y * 64, k0 = blockIdx.z * 128;
    if (tid < 32) { s_a[tid] = d_bn1a[tid]; s_c[tid] = d_bn1c[tid]; }
    __syncthreads();

    #pragma unroll
    for (int i = 0; i < 8; i++) {
        int p = tid + i * 256;
        int m = p >> 5, c4 = p & 31;
        float4 v = *(const float4*)&d_y[(size_t)(m0 + m) * FDIM + k0 + c4 * 4];
        int kk = k0 + c4 * 4;
        int ch0 = kk / 144, ch1 = (kk + 1) / 144, ch2 = (kk + 2) / 144, ch3 = (kk + 3) / 144;
        s_y[(c4 * 4 + 0) * FC_SY_STRIDE + m] = fmaxf(fmaf(v.x, s_a[ch0], s_c[ch0]), 0.f);
        s_y[(c4 * 4 + 1) * FC_SY_STRIDE + m] = fmaxf(fmaf(v.y, s_a[ch1], s_c[ch1]), 0.f);
        s_y[(c4 * 4 + 2) * FC_SY_STRIDE + m] = fmaxf(fmaf(v.z, s_a[ch2], s_c[ch2]), 0.f);
        s_y[(c4 * 4 + 3) * FC_SY_STRIDE + m] = fmaxf(fmaf(v.w, s_a[ch3], s_c[ch3]), 0.f);
    }
    #pragma unroll
    for (int i = 0; i < 16; i++) {
        int p = tid + i * 256;
        int n = p >> 5, c4 = p & 31;
        float4 v = make_float4(0.f, 0.f, 0.f, 0.f);
        if (n0 + n < EDIM) v = *(const float4*)&fc_w[(size_t)(n0 + n) * FDIM + k0 + c4 * 4];
        s_w[(c4 * 4 + 0) * FC_SW_STRIDE + n] = v.x;
        s_w[(c4 * 4 + 1) * FC_SW_STRIDE + n] = v.y;
        s_w[(c4 * 4 + 2) * FC_SW_STRIDE + n] = v.z;
        s_w[(c4 * 4 + 3) * FC_SW_STRIDE + n] = v.w;
    }
    __syncthreads();

    int mg = (tid & 15) * 4;
    int ng = (tid >> 4) * 8;
    float acc[32];
    #pragma unroll
    for (int i = 0; i < 32; i++) acc[i] = 0.f;

    #pragma unroll 8
    for (int k = 0; k < 128; k++) {
        float4 z = *(const float4*)(s_y + k * FC_SY_STRIDE + mg);
        float4 ea = *(const float4*)(s_w + k * FC_SW_STRIDE + ng);
        float4 eb = *(const float4*)(s_w + k * FC_SW_STRIDE + ng + 4);
        float zz[4] = {z.x, z.y, z.z, z.w};
        float ee[8] = {ea.x, ea.y, ea.z, ea.w, eb.x, eb.y, eb.z, eb.w};
        #pragma unroll
        for (int mi = 0; mi < 4; mi++)
            #pragma unroll
            for (int nj = 0; nj < 8; nj++)
                acc[mi * 8 + nj] = fmaf(zz[mi], ee[nj], acc[mi * 8 + nj]);
    }

    #pragma unroll
    for (int mi = 0; mi < 4; mi++)
        #pragma unroll
        for (int nj = 0; nj < 8; nj++) {
            int n = n0 + ng + nj;
            if (n < EDIM)
                atomicAdd(&d_h[(size_t)(m0 + mg + mi) * EDIM + n], acc[mi * 8 + nj]);
        }
}

// ---------------- K4: bn2 + relu, emit bf16 [z_hi | z_lo | z_hi] ----------------
__global__ void k4_bn2(const float* __restrict__ g2, const float* __restrict__ b2) {
    int n = blockIdx.x;        // feature 0..199
    int t = threadIdx.x;       // 256
    float v0 = d_h[(size_t)t * EDIM + n];
    float v1 = d_h[(size_t)(t + 256) * EDIM + n];
    __shared__ float rs[256], rq[256];
    rs[t] = v0 + v1; rq[t] = v0 * v0 + v1 * v1;
    __syncthreads();
    for (int o = 128; o; o >>= 1) {
        if (t < o) { rs[t] += rs[t + o]; rq[t] += rq[t + o]; }
        __syncthreads();
    }
    __shared__ float sa, sc;
    if (t == 0) {
        float m = rs[0] * (1.f / 512.f);
        float var = rq[0] * (1.f / 512.f) - m * m;
        float a = rsqrtf(var + EPS) * g2[n];
        sa = a; sc = b2[n] - m * a;
    }
    __syncthreads();
    float z0 = fmaxf(fmaf(v0, sa, sc), 0.f);
    float z1 = fmaxf(fmaf(v1, sa, sc), 0.f);
    __nv_bfloat16 h0 = __float2bfloat16(z0);
    __nv_bfloat16 h1 = __float2bfloat16(z1);
    __nv_bfloat16 l0 = __float2bfloat16(z0 - __bfloat162float(h0));
    __nv_bfloat16 l1 = __float2bfloat16(z1 - __bfloat162float(h1));
    size_t r0 = (size_t)t * KCAT, r1 = (size_t)(t + 256) * KCAT;
    d_zcat[r0 + n]       = h0; d_zcat[r0 + 256 + n] = l0; d_zcat[r0 + 512 + n] = h0;
    d_zcat[r1 + n]       = h1; d_zcat[r1 + 256 + n] = l1; d_zcat[r1 + 512 + n] = h1;
}

// ---------------- K4b: build e_cat = [e_hi | e_hi | e_lo] bf16 ----------------
// grid ENT_PAD/64 blocks x 256 thr: 4 threads/row, each covers 64 source cols.
__global__ void __launch_bounds__(256) k4b_ecat(const float* __restrict__ emb) {
    int row = blockIdx.x * 64 + (threadIdx.x >> 2);
    int q = threadIdx.x & 3;
    __nv_bfloat16* drow = d_ecat + (size_t)row * KCAT + q * 64;
    const float* src = emb + (size_t)row * EDIM + q * 64;
    bool rv = (row < NUM_ENT);
    #pragma unroll
    for (int vi = 0; vi < 16; vi++) {
        int k = q * 64 + vi * 4;
        float4 f = make_float4(0.f, 0.f, 0.f, 0.f);
        if (rv && k + 4 <= EDIM) f = *(const float4*)(src + vi * 4);
        __nv_bfloat16 h0 = __float2bfloat16(f.x), h1 = __float2bfloat16(f.y);
        __nv_bfloat16 h2 = __float2bfloat16(f.z), h3 = __float2bfloat16(f.w);
        uint2 hv = make_uint2(pack_bf16(h0, h1), pack_bf16(h2, h3));
        __nv_bfloat16 l0 = __float2bfloat16(f.x - __bfloat162float(h0));
        __nv_bfloat16 l1 = __float2bfloat16(f.y - __bfloat162float(h1));
        __nv_bfloat16 l2 = __float2bfloat16(f.z - __bfloat162float(h2));
        __nv_bfloat16 l3 = __float2bfloat16(f.w - __bfloat162float(h3));
        uint2 lv = make_uint2(pack_bf16(l0, l1), pack_bf16(l2, l3));
        *(uint2*)(drow + vi * 4)       = hv;
        *(uint2*)(drow + 256 + vi * 4) = hv;
        *(uint2*)(drow + 512 + vi * 4) = lv;
    }
}

// ---------------- K5: bf16 mma.sync GEMM + bias + sigmoid ----------------
// CTA tile: M=128 (batch) x N=128 (entities) x K'=768 (12 chunks of 64).
// 8 warps as 4(m) x 2(n): warp tile 32 x 64. cp.async double buffer, SW128 xor swizzle.
#define K5_CH 12
#define SMA(buf) ((buf) * 32768)
#define SMB(buf) ((buf) * 32768 + 16384)
#define K5_SMEM 65536

__device__ __forceinline__ void k5_issue(uint32_t sb, int buf, int c, int m0, int n0, int tid) {
    #pragma unroll
    for (int i = 0; i < 4; i++) {
        int idx = tid + i * 256;
        int row = idx >> 3, u = idx & 7;
        cp_async16(sb + SMA(buf) + swz(row * 128 + u * 16),
                   &d_zcat[(size_t)(m0 + row) * KCAT + c * 64 + u * 8]);
    }
    #pragma unroll
    for (int i = 0; i < 4; i++) {
        int idx = tid + i * 256;
        int row = idx >> 3, u = idx & 7;
        cp_async16(sb + SMB(buf) + swz(row * 128 + u * 16),
                   &d_ecat[(size_t)(n0 + row) * KCAT + c * 64 + u * 8]);
    }
    cp_commit();
}

__global__ void __launch_bounds__(256, 1) k5_mma(const float* __restrict__ bias_e,
                                                 float* __restrict__ out) {
    extern __shared__ char smem[];
    const uint32_t sb = smem_u32(smem);
    int tid = threadIdx.x, lane = tid & 31, wid = tid >> 5;
    int wm = wid & 3, wn = wid >> 2;
    int m0 = blockIdx.x * 128, n0 = blockIdx.y * 128;

    float acc[2][8][4];
    #pragma unroll
    for (int f = 0; f < 2; f++)
        #pragma unroll
        for (int h = 0; h < 8; h++)
            #pragma unroll
            for (int i = 0; i < 4; i++) acc[f][h][i] = 0.f;

    k5_issue(sb, 0, 0, m0, n0, tid);

    for (int c = 0; c < K5_CH; c++) {
        int buf = c & 1;
        if (c + 1 < K5_CH) {
            k5_issue(sb, buf ^ 1, c + 1, m0, n0, tid);
            asm volatile("cp.async.wait_group 1;" ::: "memory");
        } else {
            asm volatile("cp.async.wait_group 0;" ::: "memory");
        }
        __syncthreads();

        uint32_t abase = sb + SMA(buf), bbase = sb + SMB(buf);
        #pragma unroll
        for (int s = 0; s < 4; s++) {
            uint32_t a[2][4];
            #pragma unroll
            for (int f = 0; f < 2; f++) {
                int row = wm * 32 + f * 16 + (lane & 15);
                int u = s * 2 + (lane >> 4);
                ldm4(a[f], abase + swz(row * 128 + u * 16));
            }
            #pragma unroll
            for (int j = 0; j < 4; j++) {
                uint32_t b[4];
                int row = wn * 64 + j * 16 + ((lane >> 4) << 3) + (lane & 7);
                int u = s * 2 + ((lane >> 3) & 1);
                ldm4(b, bbase + swz(row * 128 + u * 16));
                #pragma unroll
                for (int g = 0; g < 2; g++) {
                    #pragma unroll
                    for (int f = 0; f < 2; f++)
                        mma16816(acc[f][j * 2 + g], a[f], b + g * 2);
                }
            }
        }
        __syncthreads();
    }

    // epilogue: c-frag (m16n8): c0,c1 row g cols 2q,2q+1; c2,c3 row g+8
    int g = lane >> 2, q = lane & 3;
    #pragma unroll
    for (int f = 0; f < 2; f++) {
        int mrow = m0 + wm * 32 + f * 16 + g;
        #pragma unroll
        for (int h = 0; h < 8; h++) {
            int n = n0 + wn * 64 + h * 8 + q * 2;
            if (n < NUM_ENT) {
                float b0 = bias_e[n], b1 = bias_e[n + 1];
                float v0 = acc[f][h][0] + b0, v1 = acc[f][h][1] + b1;
                float v2 = acc[f][h][2] + b0, v3 = acc[f][h][3] + b1;
                *(float2*)&out[(size_t)mrow * NUM_ENT + n] =
                    make_float2(1.f / (1.f + __expf(-v0)), 1.f / (1.f + __expf(-v1)));
                *(float2*)&out[(size_t)(mrow + 8) * NUM_ENT + n] =
                    make_float2(1.f / (1.f + __expf(-v2)), 1.f / (1.f + __expf(-v3)));
            }
        }
    }
}

// ---------------- launcher ----------------
extern "C" void kernel_launch(void* const* d_in, const int* in_sizes, int n_in,
                              void* d_out, int out_size) {
    const int*   e1     = (const int*)d_in[0];
    const int*   rel    = (const int*)d_in[1];
    const float* emb    = (const float*)d_in[2];
    const float* conv_w = (const float*)d_in[3];
    const float* conv_b = (const float*)d_in[4];
    const float* g0     = (const float*)d_in[5];
    const float* b0     = (const float*)d_in[6];
    const float* g1     = (const float*)d_in[7];
    const float* b1     = (const float*)d_in[8];
    const float* g2     = (const float*)d_in[9];
    const float* b2     = (const float*)d_in[10];
    const float* fc_w   = (const float*)d_in[11];
    // d_in[12] = fc_b: cancels exactly under training-mode bn2
    const float* bias_e = (const float*)d_in[13];
    float* out = (float*)d_out;

    cudaFuncSetAttribute(k3_fc,  cudaFuncAttributeMaxDynamicSharedMemorySize, FC_SMEM);
    cudaFuncSetAttribute(k5_mma, cudaFuncAttributeMaxDynamicSharedMemorySize, K5_SMEM);

    k4b_ecat<<<ENT_PAD / 64, 256>>>(emb);
    k0_zero<<<800, 256>>>();
    k1_bn0<<<1, 1024>>>(e1, emb, g0, b0);
    k2_conv<<<B, 256>>>(e1, rel, emb, conv_w, conv_b);
    k3a_bn1<<<1, 32>>>(g1, b1);
    k3_fc<<<dim3(2, 8, 36), 256, FC_SMEM>>>(fc_w);
    k4_bn2<<<EDIM, 256>>>(g2, b2);
    k5_mma<<<dim3(4, N_GRID), 256, K5_SMEM>>>(bias_e, out);
}

// round 4
// speedup vs baseline: 1.5623x; 1.4977x over previous
#include <cuda_runtime.h>
#include <cuda_bf16.h>
#include <cstdint>

#define B 512
#define EDIM 200
#define NUM_ENT 100000
#define FDIM 4608          // 32*8*18
#define EPS 1e-5f
#define KC2 512            // [hi(256) | lo(256)]
#define ENT_TILE 128
#define N_GRID ((NUM_ENT + ENT_TILE - 1) / ENT_TILE)   // 782
#define ENT_PAD (N_GRID * ENT_TILE)                    // 100096

// ---------------- device scratch (static allocations only) ----------------
__device__ float d_y[B * FDIM];            // conv output, pre-bn1
__device__ float d_h[B * EDIM];            // fc output, pre-bn2
__device__ __nv_bfloat16 d_zcat[B * KC2];          // [batch][512] = [z_hi|z_lo]
__device__ __nv_bfloat16 d_ecat[ENT_PAD * KC2];    // [ent][512]  = [e_hi|e_lo]
__device__ float d_chsum[32];
__device__ float d_chsq[32];
__device__ float d_bn0[2];
__device__ float d_bn1a[32];
__device__ float d_bn1c[32];

// ---------------- PTX helpers (sm_80-compatible subset only) ----------------
__device__ __forceinline__ uint32_t smem_u32(const void* p) {
    uint32_t a;
    asm("{ .reg .u64 t; cvta.to.shared.u64 t, %1; cvt.u32.u64 %0, t; }" : "=r"(a) : "l"(p));
    return a;
}
__device__ __forceinline__ void cp_async16(uint32_t dst, const void* src) {
    asm volatile("cp.async.cg.shared.global [%0], [%1], 16;" :: "r"(dst), "l"(src) : "memory");
}
__device__ __forceinline__ void cp_commit() {
    asm volatile("cp.async.commit_group;" ::: "memory");
}
__device__ __forceinline__ void ldm4(uint32_t* r, uint32_t a) {
    asm volatile("ldmatrix.sync.aligned.m8n8.x4.shared.b16 {%0,%1,%2,%3}, [%4];"
                 : "=r"(r[0]), "=r"(r[1]), "=r"(r[2]), "=r"(r[3]) : "r"(a));
}
__device__ __forceinline__ void mma16816(float* d, const uint32_t* a, const uint32_t* b) {
    asm volatile("mma.sync.aligned.m16n8k16.row.col.f32.bf16.bf16.f32 "
                 "{%0,%1,%2,%3}, {%4,%5,%6,%7}, {%8,%9}, {%0,%1,%2,%3};"
                 : "+f"(d[0]), "+f"(d[1]), "+f"(d[2]), "+f"(d[3])
                 : "r"(a[0]), "r"(a[1]), "r"(a[2]), "r"(a[3]), "r"(b[0]), "r"(b[1]));
}
__device__ __forceinline__ uint32_t swz(uint32_t off) { return off ^ ((off >> 3) & 0x70); }
__device__ __forceinline__ uint32_t pack_bf16(__nv_bfloat16 a, __nv_bfloat16 b) {
    return (uint32_t)__bfloat16_as_ushort(a) | ((uint32_t)__bfloat16_as_ushort(b) << 16);
}

// ---------------- K0: zero accumulators ----------------
__global__ void k0_zero() {
    int i = blockIdx.x * blockDim.x + threadIdx.x;
    if (i < B * EDIM) d_h[i] = 0.f;
    if (i < B * KC2 / 2) ((uint32_t*)d_zcat)[i] = 0u;
    if (i < 32) { d_chsum[i] = 0.f; d_chsq[i] = 0.f; }
}

// ---------------- K1: bn0 stats ----------------
__global__ void k1_bn0(const int* __restrict__ e1, const float* __restrict__ emb,
                       const float* __restrict__ g0, const float* __restrict__ b0) {
    __shared__ float rs[1024], rq[1024];
    int tid = threadIdx.x;
    float s = 0.f, q = 0.f;
    for (int idx = tid; idx < B * EDIM; idx += 1024) {
        int b = idx / EDIM, j = idx - b * EDIM;
        float v = emb[(size_t)e1[b] * EDIM + j];
        s += v; q += v * v;
    }
    rs[tid] = s; rq[tid] = q;
    __syncthreads();
    for (int o = 512; o; o >>= 1) {
        if (tid < o) { rs[tid] += rs[tid + o]; rq[tid] += rq[tid + o]; }
        __syncthreads();
    }
    if (tid == 0) {
        const float inv = 1.f / (float)(B * EDIM);
        float m = rs[0] * inv;
        float var = rq[0] * inv - m * m;
        float sc = rsqrtf(var + EPS) * g0[0];
        d_bn0[0] = sc;
        d_bn0[1] = b0[0] - m * sc;
    }
}

// ---------------- K2: relation-indexed 3x3 conv ----------------
__global__ void k2_conv(const int* __restrict__ e1, const int* __restrict__ rel,
                        const float* __restrict__ emb,
                        const float* __restrict__ conv_w, const float* __restrict__ conv_b) {
    __shared__ float sx[200];
    __shared__ float sw[288];
    __shared__ float scb[32];
    int b = blockIdx.x;
    int tid = threadIdx.x;
    int r = rel[b];
    float bn_s = d_bn0[0], bn_b = d_bn0[1];
    if (tid < 200) sx[tid] = fmaf(emb[(size_t)e1[b] * EDIM + tid], bn_s, bn_b);
    for (int i = tid; i < 288; i += 256) sw[i] = conv_w[(size_t)r * 288 + i];
    if (tid < 32) scb[tid] = conv_b[(size_t)r * 32 + tid];
    __syncthreads();

    int o = tid >> 3;
    int i = tid & 7;
    const float* w = &sw[o * 9];
    float cb = scb[o];
    float ls = 0.f, lq = 0.f;
    float* yrow = &d_y[(size_t)b * FDIM + o * 144 + i * 18];
    #pragma unroll
    for (int j = 0; j < 18; j++) {
        float acc = cb;
        #pragma unroll
        for (int di = 0; di < 3; di++)
            #pragma unroll
            for (int dj = 0; dj < 3; dj++)
                acc = fmaf(sx[(i + di) * 20 + (j + dj)], w[di * 3 + dj], acc);
        yrow[j] = acc;
        ls += acc; lq += acc * acc;
    }
    #pragma unroll
    for (int off = 4; off; off >>= 1) {
        ls += __shfl_down_sync(0xffffffffu, ls, off, 8);
        lq += __shfl_down_sync(0xffffffffu, lq, off, 8);
    }
    if ((tid & 7) == 0) {
        atomicAdd(&d_chsum[o], ls);
        atomicAdd(&d_chsq[o], lq);
    }
}

// ---------------- K3a: bn1 affine ----------------
__global__ void k3a_bn1(const float* __restrict__ g1, const float* __restrict__ b1) {
    int c = threadIdx.x;
    if (c < 32) {
        const float inv = 1.f / (float)(B * 144);
        float m = d_chsum[c] * inv;
        float var = d_chsq[c] * inv - m * m;
        float a = rsqrtf(var + EPS) * g1[c];
        d_bn1a[c] = a;
        d_bn1c[c] = b1[c] - m * a;
    }
}

// ---------------- K3: fc GEMM (fp32 SIMT, k-split atomics) ----------------
#define FC_SY_STRIDE 68
#define FC_SW_STRIDE 132
#define FC_SMEM ((128*FC_SY_STRIDE + 128*FC_SW_STRIDE) * 4)
__global__ void __launch_bounds__(256) k3_fc(const float* __restrict__ fc_w) {
    extern __shared__ float sm[];
    float* s_y = sm;
    float* s_w = sm + 128 * FC_SY_STRIDE;
    __shared__ float s_a[32], s_c[32];

    int tid = threadIdx.x;
    int n0 = blockIdx.x * 128, m0 = blockIdx.y * 64, k0 = blockIdx.z * 128;
    if (tid < 32) { s_a[tid] = d_bn1a[tid]; s_c[tid] = d_bn1c[tid]; }
    __syncthreads();

    #pragma unroll
    for (int i = 0; i < 8; i++) {
        int p = tid + i * 256;
        int m = p >> 5, c4 = p & 31;
        float4 v = *(const float4*)&d_y[(size_t)(m0 + m) * FDIM + k0 + c4 * 4];
        int kk = k0 + c4 * 4;
        int ch0 = kk / 144, ch1 = (kk + 1) / 144, ch2 = (kk + 2) / 144, ch3 = (kk + 3) / 144;
        s_y[(c4 * 4 + 0) * FC_SY_STRIDE + m] = fmaxf(fmaf(v.x, s_a[ch0], s_c[ch0]), 0.f);
        s_y[(c4 * 4 + 1) * FC_SY_STRIDE + m] = fmaxf(fmaf(v.y, s_a[ch1], s_c[ch1]), 0.f);
        s_y[(c4 * 4 + 2) * FC_SY_STRIDE + m] = fmaxf(fmaf(v.z, s_a[ch2], s_c[ch2]), 0.f);
        s_y[(c4 * 4 + 3) * FC_SY_STRIDE + m] = fmaxf(fmaf(v.w, s_a[ch3], s_c[ch3]), 0.f);
    }
    #pragma unroll
    for (int i = 0; i < 16; i++) {
        int p = tid + i * 256;
        int n = p >> 5, c4 = p & 31;
        float4 v = make_float4(0.f, 0.f, 0.f, 0.f);
        if (n0 + n < EDIM) v = *(const float4*)&fc_w[(size_t)(n0 + n) * FDIM + k0 + c4 * 4];
        s_w[(c4 * 4 + 0) * FC_SW_STRIDE + n] = v.x;
        s_w[(c4 * 4 + 1) * FC_SW_STRIDE + n] = v.y;
        s_w[(c4 * 4 + 2) * FC_SW_STRIDE + n] = v.z;
        s_w[(c4 * 4 + 3) * FC_SW_STRIDE + n] = v.w;
    }
    __syncthreads();

    int mg = (tid & 15) * 4;
    int ng = (tid >> 4) * 8;
    float acc[32];
    #pragma unroll
    for (int i = 0; i < 32; i++) acc[i] = 0.f;

    #pragma unroll 8
    for (int k = 0; k < 128; k++) {
        float4 z = *(const float4*)(s_y + k * FC_SY_STRIDE + mg);
        float4 ea = *(const float4*)(s_w + k * FC_SW_STRIDE + ng);
        float4 eb = *(const float4*)(s_w + k * FC_SW_STRIDE + ng + 4);
        float zz[4] = {z.x, z.y, z.z, z.w};
        float ee[8] = {ea.x, ea.y, ea.z, ea.w, eb.x, eb.y, eb.z, eb.w};
        #pragma unroll
        for (int mi = 0; mi < 4; mi++)
            #pragma unroll
            for (int nj = 0; nj < 8; nj++)
                acc[mi * 8 + nj] = fmaf(zz[mi], ee[nj], acc[mi * 8 + nj]);
    }

    #pragma unroll
    for (int mi = 0; mi < 4; mi++)
        #pragma unroll
        for (int nj = 0; nj < 8; nj++) {
            int n = n0 + ng + nj;
            if (n < EDIM)
                atomicAdd(&d_h[(size_t)(m0 + mg + mi) * EDIM + n], acc[mi * 8 + nj]);
        }
}

// ---------------- K4: bn2 + relu, emit bf16 [z_hi | z_lo] ----------------
__global__ void k4_bn2(const float* __restrict__ g2, const float* __restrict__ b2) {
    int n = blockIdx.x;        // feature 0..199
    int t = threadIdx.x;       // 256
    float v0 = d_h[(size_t)t * EDIM + n];
    float v1 = d_h[(size_t)(t + 256) * EDIM + n];
    __shared__ float rs[256], rq[256];
    rs[t] = v0 + v1; rq[t] = v0 * v0 + v1 * v1;
    __syncthreads();
    for (int o = 128; o; o >>= 1) {
        if (t < o) { rs[t] += rs[t + o]; rq[t] += rq[t + o]; }
        __syncthreads();
    }
    __shared__ float sa, sc;
    if (t == 0) {
        float m = rs[0] * (1.f / 512.f);
        float var = rq[0] * (1.f / 512.f) - m * m;
        float a = rsqrtf(var + EPS) * g2[n];
        sa = a; sc = b2[n] - m * a;
    }
    __syncthreads();
    float z0 = fmaxf(fmaf(v0, sa, sc), 0.f);
    float z1 = fmaxf(fmaf(v1, sa, sc), 0.f);
    __nv_bfloat16 h0 = __float2bfloat16(z0);
    __nv_bfloat16 h1 = __float2bfloat16(z1);
    __nv_bfloat16 l0 = __float2bfloat16(z0 - __bfloat162float(h0));
    __nv_bfloat16 l1 = __float2bfloat16(z1 - __bfloat162float(h1));
    size_t r0 = (size_t)t * KC2, r1 = (size_t)(t + 256) * KC2;
    d_zcat[r0 + n] = h0; d_zcat[r0 + 256 + n] = l0;
    d_zcat[r1 + n] = h1; d_zcat[r1 + 256 + n] = l1;
}

// ---------------- K4b: build e_cat = [e_hi | e_lo], fully coalesced ----------------
// 782 blocks x 256 thr. Warp handles one row per iter; lane covers 8 cols.
__global__ void __launch_bounds__(256) k4b_ecat(const float* __restrict__ emb) {
    int warp = threadIdx.x >> 5, lane = threadIdx.x & 31;
    int row0 = blockIdx.x * 128;
    #pragma unroll 4
    for (int it = 0; it < 16; it++) {
        int row = row0 + warp + it * 8;
        bool rv = (row < NUM_ENT) && (lane < 25);     // 25*8 = 200 cols
        float4 f0 = make_float4(0.f, 0.f, 0.f, 0.f);
        float4 f1 = make_float4(0.f, 0.f, 0.f, 0.f);
        if (rv) {
            const float* src = emb + (size_t)row * EDIM + lane * 8;
            f0 = *(const float4*)src;
            f1 = *(const float4*)(src + 4);
        }
        float v[8] = {f0.x, f0.y, f0.z, f0.w, f1.x, f1.y, f1.z, f1.w};
        uint32_t hp[4], lp[4];
        #pragma unroll
        for (int i = 0; i < 4; i++) {
            __nv_bfloat16 ha = __float2bfloat16(v[2 * i]);
            __nv_bfloat16 hb = __float2bfloat16(v[2 * i + 1]);
            hp[i] = pack_bf16(ha, hb);
            lp[i] = pack_bf16(__float2bfloat16(v[2 * i]     - __bfloat162float(ha)),
                              __float2bfloat16(v[2 * i + 1] - __bfloat162float(hb)));
        }
        __nv_bfloat16* dr = d_ecat + (size_t)row * KC2;
        *(uint4*)(dr + lane * 8)       = make_uint4(hp[0], hp[1], hp[2], hp[3]);
        *(uint4*)(dr + 256 + lane * 8) = make_uint4(lp[0], lp[1], lp[2], lp[3]);
    }
}

// ---------------- K5: bf16 mma.sync GEMM + bias + sigmoid ----------------
// CTA tile: M=128 (batch) x N=128 (ent). Per k-quarter ks (64 cols), load
// {A_hi, A_lo, B_hi, B_lo} once and run 3 passes: zhi*ehi, zlo*ehi, zhi*elo.
// ks=3 has only 8 real cols (192..199) -> 1 k16-step instead of 4.
#define T_AH 0
#define T_AL 16384
#define T_BH 32768
#define T_BL 49152
#define ST_STRIDE 65536
#define K5_SMEM 131072

__device__ __forceinline__ void k5_load(uint32_t sb, int buf, int ks, int m0, int n0, int tid) {
    uint32_t base = sb + buf * ST_STRIDE;
    int koff = ks * 64;
    #pragma unroll
    for (int i = 0; i < 4; i++) {
        int idx = tid + i * 256;
        int row = idx >> 3, u = idx & 7;
        uint32_t so = swz(row * 128 + u * 16);
        const __nv_bfloat16* zr = d_zcat + (size_t)(m0 + row) * KC2 + koff + u * 8;
        cp_async16(base + T_AH + so, zr);
        cp_async16(base + T_AL + so, zr + 256);
        const __nv_bfloat16* er = d_ecat + (size_t)(n0 + row) * KC2 + koff + u * 8;
        cp_async16(base + T_BH + so, er);
        cp_async16(base + T_BL + so, er + 256);
    }
    cp_commit();
}

__global__ void __launch_bounds__(256, 1) k5_mma(const float* __restrict__ bias_e,
                                                 float* __restrict__ out) {
    extern __shared__ char smem[];
    const uint32_t sb = smem_u32(smem);
    int tid = threadIdx.x, lane = tid & 31, wid = tid >> 5;
    int wm = wid & 3, wn = wid >> 2;
    int m0 = blockIdx.x * 128, n0 = blockIdx.y * 128;

    float acc[2][8][4];
    #pragma unroll
    for (int f = 0; f < 2; f++)
        #pragma unroll
        for (int h = 0; h < 8; h++)
            #pragma unroll
            for (int i = 0; i < 4; i++) acc[f][h][i] = 0.f;

    k5_load(sb, 0, 0, m0, n0, tid);

    for (int ks = 0; ks < 4; ks++) {
        int buf = ks & 1;
        if (ks < 3) {
            k5_load(sb, buf ^ 1, ks + 1, m0, n0, tid);
            asm volatile("cp.async.wait_group 1;" ::: "memory");
        } else {
            asm volatile("cp.async.wait_group 0;" ::: "memory");
        }
        __syncthreads();

        const int scount = (ks < 3) ? 4 : 1;
        const uint32_t st = sb + buf * ST_STRIDE;
        #pragma unroll
        for (int pass = 0; pass < 3; pass++) {
            uint32_t abase = st + (pass == 1 ? T_AL : T_AH);
            uint32_t bbase = st + (pass == 2 ? T_BL : T_BH);
            for (int s = 0; s < scount; s++) {
                uint32_t a[2][4];
                #pragma unroll
                for (int f = 0; f < 2; f++) {
                    int row = wm * 32 + f * 16 + (lane & 15);
                    int u = s * 2 + (lane >> 4);
                    ldm4(a[f], abase + swz(row * 128 + u * 16));
                }
                #pragma unroll
                for (int j = 0; j < 4; j++) {
                    uint32_t b[4];
                    int row = wn * 64 + j * 16 + ((lane >> 4) << 3) + (lane & 7);
                    int u = s * 2 + ((lane >> 3) & 1);
                    ldm4(b, bbase + swz(row * 128 + u * 16));
                    #pragma unroll
                    for (int g = 0; g < 2; g++)
                        #pragma unroll
                        for (int f = 0; f < 2; f++)
                            mma16816(acc[f][j * 2 + g], a[f], b + g * 2);
                }
            }
        }
        __syncthreads();
    }

    // epilogue: c-frag (m16n8): c0,c1 row g cols 2q,2q+1; c2,c3 row g+8
    int g = lane >> 2, q = lane & 3;
    #pragma unroll
    for (int f = 0; f < 2; f++) {
        int mrow = m0 + wm * 32 + f * 16 + g;
        #pragma unroll
        for (int h = 0; h < 8; h++) {
            int n = n0 + wn * 64 + h * 8 + q * 2;
            if (n < NUM_ENT) {
                float b0 = bias_e[n], b1 = bias_e[n + 1];
                float v0 = acc[f][h][0] + b0, v1 = acc[f][h][1] + b1;
                float v2 = acc[f][h][2] + b0, v3 = acc[f][h][3] + b1;
                *(float2*)&out[(size_t)mrow * NUM_ENT + n] =
                    make_float2(1.f / (1.f + __expf(-v0)), 1.f / (1.f + __expf(-v1)));
                *(float2*)&out[(size_t)(mrow + 8) * NUM_ENT + n] =
                    make_float2(1.f / (1.f + __expf(-v2)), 1.f / (1.f + __expf(-v3)));
            }
        }
    }
}

// ---------------- launcher ----------------
extern "C" void kernel_launch(void* const* d_in, const int* in_sizes, int n_in,
                              void* d_out, int out_size) {
    const int*   e1     = (const int*)d_in[0];
    const int*   rel    = (const int*)d_in[1];
    const float* emb    = (const float*)d_in[2];
    const float* conv_w = (const float*)d_in[3];
    const float* conv_b = (const float*)d_in[4];
    const float* g0     = (const float*)d_in[5];
    const float* b0     = (const float*)d_in[6];
    const float* g1     = (const float*)d_in[7];
    const float* b1     = (const float*)d_in[8];
    const float* g2     = (const float*)d_in[9];
    const float* b2     = (const float*)d_in[10];
    const float* fc_w   = (const float*)d_in[11];
    // d_in[12] = fc_b: cancels exactly under training-mode bn2
    const float* bias_e = (const float*)d_in[13];
    float* out = (float*)d_out;

    cudaFuncSetAttribute(k3_fc,  cudaFuncAttributeMaxDynamicSharedMemorySize, FC_SMEM);
    cudaFuncSetAttribute(k5_mma, cudaFuncAttributeMaxDynamicSharedMemorySize, K5_SMEM);

    k4b_ecat<<<N_GRID, 256>>>(emb);
    k0_zero<<<800, 256>>>();
    k1_bn0<<<1, 1024>>>(e1, emb, g0, b0);
    k2_conv<<<B, 256>>>(e1, rel, emb, conv_w, conv_b);
    k3a_bn1<<<1, 32>>>(g1, b1);
    k3_fc<<<dim3(2, 8, 36), 256, FC_SMEM>>>(fc_w);
    k4_bn2<<<EDIM, 256>>>(g2, b2);
    k5_mma<<<dim3(4, N_GRID), 256, K5_SMEM>>>(bias_e, out);
}